// round 3
// baseline (speedup 1.0000x reference)
#include <cuda_runtime.h>
#include <cuda_fp16.h>
#include <mma.h>

using namespace nvcuda;

// Problem constants
#define B_    32
#define C_    256
#define H_    56
#define W_    56
#define HW_   3136            // 56*56
#define O_    512
#define KK_   2304            // C*9
#define NPIX  100352          // B*HW

// GEMM tiling
#define BM 64
#define BN 128
#define BK 16

// Scratch (device globals — no allocation at runtime)
__device__ __half d_Wh[O_ * KK_];              // weights fp16, [o][k] row-major
__device__ __half d_xh[B_ * C_ * HW_];         // x fp16, same layout as x
__device__ int    d_mask_kind;                 // 0=uint8, 1=int32, 2=float32

// ---------------------------------------------------------------------------
// Detect how the boolean masks are materialized on device.
// Scans the first 4096 uint32 words of `pos`:
//   - words == 0x3F800000 present           -> float32 0/1
//   - otherwise any word > 1                -> packed uint8 bytes
//   - all words in {0,1}                    -> int32 0/1
// ---------------------------------------------------------------------------
__global__ void detect_mask_kernel(const unsigned int* __restrict__ pos) {
    __shared__ int any_big;
    __shared__ int any_f32;
    if (threadIdx.x == 0) { any_big = 0; any_f32 = 0; }
    __syncthreads();
    for (int i = threadIdx.x; i < 4096; i += 256) {
        unsigned int v = pos[i];
        if (v == 0x3F800000u) any_f32 = 1;
        else if (v > 1u)      any_big = 1;
    }
    __syncthreads();
    if (threadIdx.x == 0) {
        d_mask_kind = any_f32 ? 2 : (any_big ? 0 : 1);
    }
}

// ---------------------------------------------------------------------------
// Preprocess: ternary masks -> fp16 weight matrix [O][K]
// masks are (K, O) row-major bools: logical idx = k*O + o
// ---------------------------------------------------------------------------
__global__ void prep_w_kernel(const void* __restrict__ posv,
                              const void* __restrict__ negv) {
    int i = blockIdx.x * 256 + threadIdx.x;   // over K*O = 1179648
    if (i >= KK_ * O_) return;
    int k = i / O_;
    int o = i - k * O_;
    float p, n;
    int kind = d_mask_kind;
    if (kind == 1) {
        p = (float)((const int*)posv)[i];
        n = (float)((const int*)negv)[i];
    } else if (kind == 2) {
        p = ((const float*)posv)[i];
        n = ((const float*)negv)[i];
    } else {
        p = (float)((const unsigned char*)posv)[i];
        n = (float)((const unsigned char*)negv)[i];
    }
    d_Wh[o * KK_ + k] = __float2half(p - n);
}

// ---------------------------------------------------------------------------
// Preprocess: x fp32 -> fp16 (vectorized 4 at a time; count divisible by 4)
// ---------------------------------------------------------------------------
__global__ void prep_x_kernel(const float* __restrict__ x) {
    int i4 = blockIdx.x * 256 + threadIdx.x;          // 6422528 total
    const float4 v = reinterpret_cast<const float4*>(x)[i4];
    __half2 a = __floats2half2_rn(v.x, v.y);
    __half2 b = __floats2half2_rn(v.z, v.w);
    uint2 packed;
    packed.x = *reinterpret_cast<unsigned int*>(&a);
    packed.y = *reinterpret_cast<unsigned int*>(&b);
    reinterpret_cast<uint2*>(d_xh)[i4] = packed;
}

// ---------------------------------------------------------------------------
// Implicit-GEMM conv: out[m, n] = sum_k Wh[m][k] * im2col(x)[k][n]
//   m = output channel, n = flattened (b, h, w), k = c*9 + (kh*3+kw)
// Block: 256 threads = 8 warps (2x4 warp grid), tile BM=64 x BN=128, BK=16.
// Each warp: 32x32 via 2x2 wmma 16x16x16 fragments (fp16 in, fp32 acc).
// ---------------------------------------------------------------------------
__global__ __launch_bounds__(256) void conv_gemm_kernel(float* __restrict__ out) {
    __shared__ __align__(32) __half As[BM][BK];        // [m][k]
    __shared__ __align__(32) __half Bs[BK][BN + 8];    // [k][n], padded
    __shared__ __align__(32) float  Cs[32][BN + 4];    // epilogue staging (half of BM)
    __shared__ int   sOff[BN];    // b*C*HW + hw   (x base offset sans channel)
    __shared__ int   sOut[BN];    // b*O*HW + hw   (out base offset sans channel)
    __shared__ short sH[BN];
    __shared__ short sW[BN];

    const int tid = threadIdx.x;
    const int n0 = blockIdx.x * BN;    // pixel tile
    const int m0 = blockIdx.y * BM;    // output-channel tile

    // Per-pixel metadata (computed once per block)
    if (tid < BN) {
        int n  = n0 + tid;
        int b  = n / HW_;
        int hw = n - b * HW_;
        int h  = hw / W_;
        int w  = hw - h * W_;
        sOff[tid] = b * (C_ * HW_) + hw;
        sOut[tid] = b * (O_ * HW_) + hw;
        sH[tid] = (short)h;
        sW[tid] = (short)w;
    }
    __syncthreads();

    const int wid  = tid >> 5;
    const int wm   = wid >> 2;        // 0..1  (M direction)
    const int wn   = wid & 3;         // 0..3  (N direction)

    // Gather mapping: 16 k-rows x 16 thread-groups x 8 pixels
    const int gr  = tid >> 4;         // k row 0..15
    const int gj0 = (tid & 15) * 8;   // starting pixel col

    wmma::fragment<wmma::accumulator, 16, 16, 16, float> acc[2][2];
#pragma unroll
    for (int i = 0; i < 2; ++i)
#pragma unroll
        for (int j = 0; j < 2; ++j)
            wmma::fill_fragment(acc[i][j], 0.0f);

    for (int k0 = 0; k0 < KK_; k0 += BK) {
        // ---- Load A tile: 64x16 halfs; each thread 4 consecutive halfs ----
        {
            int i  = tid * 4;            // 0..1020
            int m  = i >> 4;
            int kk = i & 15;
            const __half* src = d_Wh + (m0 + m) * KK_ + (k0 + kk);
            *reinterpret_cast<uint2*>(&As[m][kk]) =
                *reinterpret_cast<const uint2*>(src);
        }
        // ---- Gather B tile (im2col on the fly): 16x128 halfs ----
        {
            int k  = k0 + gr;
            int c  = k / 9;
            int t  = k - c * 9;
            int th = t / 3;
            int dh = th - 1;
            int dw = (t - th * 3) - 1;
            int coff = c * HW_ + dh * W_ + dw;
#pragma unroll
            for (int jj = 0; jj < 8; ++jj) {
                int j  = gj0 + jj;
                int hh = sH[j] + dh;
                int ww = sW[j] + dw;
                __half v = __ushort_as_half((unsigned short)0);
                if ((unsigned)hh < (unsigned)H_ && (unsigned)ww < (unsigned)W_)
                    v = d_xh[sOff[j] + coff];
                Bs[gr][j] = v;
            }
        }
        __syncthreads();

        // ---- MMA: each warp 2x2 fragments of 16x16x16 ----
#pragma unroll
        for (int i = 0; i < 2; ++i) {
            wmma::fragment<wmma::matrix_a, 16, 16, 16, __half, wmma::row_major> afrag;
            wmma::load_matrix_sync(afrag, &As[wm * 32 + i * 16][0], BK);
#pragma unroll
            for (int j = 0; j < 2; ++j) {
                wmma::fragment<wmma::matrix_b, 16, 16, 16, __half, wmma::row_major> bfrag;
                wmma::load_matrix_sync(bfrag, &Bs[0][wn * 32 + j * 16], BN + 8);
                wmma::mma_sync(acc[i][j], afrag, bfrag, acc[i][j]);
            }
        }
        __syncthreads();
    }

    // ---- Epilogue: two passes of 32 M-rows through SMEM, scatter to NCHW ----
#pragma unroll
    for (int pass = 0; pass < 2; ++pass) {
        if (wm == pass) {
#pragma unroll
            for (int i = 0; i < 2; ++i)
#pragma unroll
                for (int j = 0; j < 2; ++j)
                    wmma::store_matrix_sync(&Cs[i * 16][wn * 32 + j * 16],
                                            acc[i][j], BN + 4,
                                            wmma::mem_row_major);
        }
        __syncthreads();
#pragma unroll 4
        for (int e = tid; e < 32 * BN; e += 256) {
            int m = e >> 7;        // /128
            int j = e & 127;
            out[sOut[j] + (m0 + pass * 32 + m) * HW_] = Cs[m][j];
        }
        __syncthreads();
    }
}

// ---------------------------------------------------------------------------
// Launch
// ---------------------------------------------------------------------------
extern "C" void kernel_launch(void* const* d_in, const int* in_sizes, int n_in,
                              void* d_out, int out_size) {
    const float*         x   = (const float*)d_in[0];
    const void*          pos = d_in[1];
    const void*          neg = d_in[2];
    float* out = (float*)d_out;

    // 0) sniff the device representation of the boolean masks
    detect_mask_kernel<<<1, 256>>>((const unsigned int*)pos);
    // 1) weights -> fp16 [O][K]
    prep_w_kernel<<<(KK_ * O_ + 255) / 256, 256>>>(pos, neg);
    // 2) x -> fp16 (25690112 elems / 4 per thread = 6422528 threads)
    prep_x_kernel<<<6422528 / 256, 256>>>(x);
    // 3) implicit GEMM: grid = (N tiles, M tiles) = (784, 8)
    dim3 grid(NPIX / BN, O_ / BM);
    conv_gemm_kernel<<<grid, 256>>>(out);
}

// round 5
// speedup vs baseline: 5.0339x; 5.0339x over previous
#include <cuda_runtime.h>
#include <cuda_fp16.h>
#include <mma.h>
#include <cstdint>

using namespace nvcuda;

// ---------------------------------------------------------------------------
// Problem constants
// ---------------------------------------------------------------------------
#define B_    32
#define C_    256
#define H_    56
#define W_    56
#define HW_   3136            // 56*56
#define O_    512
#define KK_   2304            // C*9
#define NPIX  100352          // B*HW

// GEMM tiling
#define BM 128
#define BN 256
#define BK 32
#define NCHUNK 72             // 2304 / 32
#define NTHREADS 512

// SMEM stage layout: A 128 rows x 80B, B 256 rows x 80B  (row = 32 halfs + 8 pad)
#define A_BYTES   (128 * 80)          // 10240
#define B_BYTES   (256 * 80)          // 20480
#define STAGE_B   (A_BYTES + B_BYTES) // 30720
#define NSTAGES   4
#define SM_META   (NSTAGES * STAGE_B) // 122880
#define SMEM_TOTAL (SM_META + 2560)

// ---------------------------------------------------------------------------
// Device scratch (no runtime allocation)
// ---------------------------------------------------------------------------
__device__ __half d_Wh[O_ * KK_];     // weights fp16, [o][k'], k' = tap*256 + c
#define XPAD 16384
__device__ __half d_xt_buf[XPAD + (size_t)B_ * HW_ * C_ + XPAD]; // x^T: [b][hw][c]
__device__ int    d_mask_kind;        // 0=uint8, 1=int32, 2=float32

// ---------------------------------------------------------------------------
// Helpers
// ---------------------------------------------------------------------------
__device__ __forceinline__ uint32_t smem_to_u32(const void* p) {
    uint32_t a;
    asm("{ .reg .u64 t; cvta.to.shared.u64 t, %1; cvt.u32.u64 %0, t; }" : "=r"(a) : "l"(p));
    return a;
}

__device__ __forceinline__ void cp_async16(uint32_t dst, const void* src, int src_size) {
    asm volatile("cp.async.cg.shared.global [%0], [%1], 16, %2;"
                 :: "r"(dst), "l"(src), "r"(src_size) : "memory");
}
__device__ __forceinline__ void cp_commit() {
    asm volatile("cp.async.commit_group;" ::: "memory");
}
__device__ __forceinline__ void cp_wait2() {
    asm volatile("cp.async.wait_group 2;" ::: "memory");
}

// ---------------------------------------------------------------------------
// Mask dtype sniffing (unchanged from passing round)
// ---------------------------------------------------------------------------
__global__ void detect_mask_kernel(const unsigned int* __restrict__ pos) {
    __shared__ int any_big;
    __shared__ int any_f32;
    if (threadIdx.x == 0) { any_big = 0; any_f32 = 0; }
    __syncthreads();
    for (int i = threadIdx.x; i < 4096; i += 256) {
        unsigned int v = pos[i];
        if (v == 0x3F800000u) any_f32 = 1;
        else if (v > 1u)      any_big = 1;
    }
    __syncthreads();
    if (threadIdx.x == 0) d_mask_kind = any_f32 ? 2 : (any_big ? 0 : 1);
}

// ---------------------------------------------------------------------------
// Weights: masks (K,O) -> fp16 [o][k'] with k' = tap*256 + c   (k = c*9 + tap)
// ---------------------------------------------------------------------------
__global__ void prep_w_kernel(const void* __restrict__ posv,
                              const void* __restrict__ negv) {
    int i = blockIdx.x * 256 + threadIdx.x;   // over K*O
    if (i >= KK_ * O_) return;
    int k = i / O_;
    int o = i - k * O_;
    float p, n;
    int kind = d_mask_kind;
    if (kind == 1)      { p = (float)((const int*)posv)[i];   n = (float)((const int*)negv)[i]; }
    else if (kind == 2) { p = ((const float*)posv)[i];        n = ((const float*)negv)[i]; }
    else                { p = (float)((const unsigned char*)posv)[i];
                          n = (float)((const unsigned char*)negv)[i]; }
    int c = k / 9;
    int t = k - c * 9;
    d_Wh[o * KK_ + t * 256 + c] = __float2half(p - n);
}

// ---------------------------------------------------------------------------
// x (b,c,hw) fp32 -> x^T (b,hw,c) fp16, tiled SMEM transpose
// grid (HW/32, C/32, B), block (32, 8)
// ---------------------------------------------------------------------------
__global__ void prep_xt_kernel(const float* __restrict__ x) {
    __shared__ __half tile[32][33];
    int hw0 = blockIdx.x * 32;
    int c0  = blockIdx.y * 32;
    int b   = blockIdx.z;
    int tx = threadIdx.x, ty = threadIdx.y;
    const float* xp = x + (size_t)b * C_ * HW_;
#pragma unroll
    for (int r = 0; r < 32; r += 8)
        tile[ty + r][tx] = __float2half(xp[(size_t)(c0 + ty + r) * HW_ + hw0 + tx]);
    __syncthreads();
    __half* xt = d_xt_buf + XPAD + (size_t)b * HW_ * C_;
#pragma unroll
    for (int r = 0; r < 32; r += 8)
        xt[(size_t)(hw0 + ty + r) * C_ + c0 + tx] = tile[tx][ty + r];
}

// ---------------------------------------------------------------------------
// Implicit-GEMM conv, wmma + 4-stage cp.async pipeline.
// CTA: BM=128 o-channels x BN=256 pixels. 16 warps, warp grid 4(M) x 4(N),
// warp tile 32x64 -> acc[2][4] wmma 16x16x16 fragments (f16 in, f32 acc).
// K chunks: 72 x 32 (one tap x 32 contiguous channels in x^T layout).
// ---------------------------------------------------------------------------
__global__ __launch_bounds__(NTHREADS, 1)
void conv_gemm_kernel(float* __restrict__ out) {
    extern __shared__ __align__(1024) char smem[];
    const uint32_t smem_base = smem_to_u32(smem);
    const int tid = threadIdx.x;

    int* sXoff = (int*)(smem + SM_META);           // (b*HW + hw) * C
    int* sHW   = (int*)(smem + SM_META + 1024);    // h<<16 | w
    int* sNB   = (int*)(smem + SM_META + 2048);    // per 4-pixel group: b*O*HW + hw

    const int n0 = blockIdx.x * BN;    // pixel tile
    const int m0 = blockIdx.y * BM;    // output-channel tile

    if (tid < BN) {
        int n  = n0 + tid;
        int b  = n / HW_;
        int hw = n - b * HW_;
        int h  = hw / W_;
        int w  = hw - h * W_;
        sXoff[tid] = (b * HW_ + hw) * C_;
        sHW[tid]   = (h << 16) | w;
    }
    if (tid < BN / 4) {
        int n  = n0 + 4 * tid;
        int b  = n / HW_;
        int hw = n - b * HW_;
        sNB[tid] = b * (O_ * HW_) + hw;
    }
    __syncthreads();

    // ---- stage loader: chunk i -> stage i&3 ----
    auto issue_loads = [&](int i) {
        const int s  = i & 3;
        const int t  = i >> 3;              // tap 0..8
        const int c0 = (i & 7) * BK;        // channel offset 0..224
        const int dh = t / 3 - 1;
        const int dw = t - (t / 3) * 3 - 1;
        // A: 512 tasks of 16B (128 rows x 4 segs); one per thread
        {
            int m   = tid >> 2;
            int seg = tid & 3;
            uint32_t dst = smem_base + s * STAGE_B + m * 80 + seg * 16;
            const __half* src = d_Wh + (size_t)(m0 + m) * KK_ + t * 256 + c0 + seg * 8;
            cp_async16(dst, src, 16);
        }
        // B: 1024 tasks of 16B (256 pixel-rows x 4 segs); two per thread
        {
            const int tapd = (dh * W_ + dw) * C_;
#pragma unroll
            for (int r = 0; r < 2; ++r) {
                int idx = tid + NTHREADS * r;
                int j   = idx >> 2;
                int seg = idx & 3;
                int hwp = sHW[j];
                int h = hwp >> 16, w = hwp & 0xFFFF;
                int valid = ((unsigned)(h + dh) < (unsigned)H_ &&
                             (unsigned)(w + dw) < (unsigned)W_) ? 16 : 0;
                uint32_t dst = smem_base + s * STAGE_B + A_BYTES + j * 80 + seg * 16;
                const __half* src = d_xt_buf + XPAD + sXoff[j] + tapd + c0 + seg * 8;
                cp_async16(dst, src, valid);
            }
        }
    };

    const int wid = tid >> 5;
    const int wm  = wid >> 2;   // 0..3 (M)
    const int wn  = wid & 3;    // 0..3 (N)

    wmma::fragment<wmma::accumulator, 16, 16, 16, float> acc[2][4];
#pragma unroll
    for (int im = 0; im < 2; ++im)
#pragma unroll
        for (int in = 0; in < 4; ++in)
            wmma::fill_fragment(acc[im][in], 0.0f);

    // ---- prologue: 3 stages in flight ----
#pragma unroll
    for (int i = 0; i < NSTAGES - 1; ++i) { issue_loads(i); cp_commit(); }

    // ---- main loop ----
    for (int i = 0; i < NCHUNK; ++i) {
        cp_wait2();
        __syncthreads();

        const int s = i & 3;
        const __half* as = (const __half*)(smem + s * STAGE_B);
        const __half* bs = (const __half*)(smem + s * STAGE_B + A_BYTES);
#pragma unroll
        for (int kk = 0; kk < BK; kk += 16) {
            wmma::fragment<wmma::matrix_a, 16, 16, 16, __half, wmma::row_major> af[2];
            wmma::fragment<wmma::matrix_b, 16, 16, 16, __half, wmma::col_major> bf[4];
#pragma unroll
            for (int im = 0; im < 2; ++im)
                wmma::load_matrix_sync(af[im], as + (wm * 32 + im * 16) * 40 + kk, 40);
#pragma unroll
            for (int in = 0; in < 4; ++in)
                wmma::load_matrix_sync(bf[in], bs + (wn * 64 + in * 16) * 40 + kk, 40);
#pragma unroll
            for (int im = 0; im < 2; ++im)
#pragma unroll
                for (int in = 0; in < 4; ++in)
                    wmma::mma_sync(acc[im][in], af[im], bf[in], acc[im][in]);
        }

        if (i + NSTAGES - 1 < NCHUNK) issue_loads(i + NSTAGES - 1);
        cp_commit();   // always commit (possibly empty group) to keep wait_group math exact
    }
    __syncthreads();

    // ---- epilogue: 4 passes of 32 M-rows through SMEM, float4 scatter ----
    float* Cs = (float*)smem;   // [32][260]
#pragma unroll 1
    for (int pass = 0; pass < 4; ++pass) {
        if (wm == pass) {
#pragma unroll
            for (int im = 0; im < 2; ++im)
#pragma unroll
                for (int in = 0; in < 4; ++in)
                    wmma::store_matrix_sync(Cs + (im * 16) * 260 + wn * 64 + in * 16,
                                            acc[im][in], 260, wmma::mem_row_major);
        }
        __syncthreads();
#pragma unroll
        for (int r = 0; r < 4; ++r) {
            int e = tid + NTHREADS * r;       // 2048 float4 tasks
            int m = e >> 6;                   // 0..31
            int q = e & 63;                   // 4-pixel group
            float4 v = *(const float4*)(Cs + m * 260 + q * 4);
            *(float4*)(out + sNB[q] + (size_t)(m0 + pass * 32 + m) * HW_) = v;
        }
        __syncthreads();
    }
}

// ---------------------------------------------------------------------------
// Launch
// ---------------------------------------------------------------------------
extern "C" void kernel_launch(void* const* d_in, const int* in_sizes, int n_in,
                              void* d_out, int out_size) {
    const float* x   = (const float*)d_in[0];
    const void*  pos = d_in[1];
    const void*  neg = d_in[2];
    float* out = (float*)d_out;

    static bool attr_set = false;
    if (!attr_set) {
        cudaFuncSetAttribute(conv_gemm_kernel,
                             cudaFuncAttributeMaxDynamicSharedMemorySize, SMEM_TOTAL);
        attr_set = true;
    }

    // 0) sniff mask representation
    detect_mask_kernel<<<1, 256>>>((const unsigned int*)pos);
    // 1) weights -> fp16 [o][k'] (tap-major K permutation)
    prep_w_kernel<<<(KK_ * O_ + 255) / 256, 256>>>(pos, neg);
    // 2) x -> fp16 transposed [b][hw][c]
    dim3 tgrid(HW_ / 32, C_ / 32, B_);
    prep_xt_kernel<<<tgrid, dim3(32, 8)>>>(x);
    // 3) wmma implicit GEMM: grid = (392 pixel tiles, 4 m tiles)
    dim3 grid(NPIX / BN, O_ / BM);
    conv_gemm_kernel<<<grid, NTHREADS, SMEM_TOTAL>>>(out);
}

// round 6
// speedup vs baseline: 5.8770x; 1.1675x over previous
#include <cuda_runtime.h>
#include <cuda_fp16.h>
#include <mma.h>
#include <cstdint>

using namespace nvcuda;

// ---------------------------------------------------------------------------
// Problem constants
// ---------------------------------------------------------------------------
#define B_    32
#define C_    256
#define H_    56
#define W_    56
#define HW_   3136            // 56*56
#define O_    512
#define KK_   2304            // C*9
#define NPIX  100352          // B*HW

// GEMM tiling
#define BM 128
#define BN 128
#define BK 32
#define NCHUNK 72             // 2304 / 32
#define NTHREADS 256

// SMEM stage layout: A 128 rows x 80B, B 128 rows x 80B (row = 32 halfs + 8 pad)
#define A_BYTES   (128 * 80)          // 10240
#define B_BYTES   (128 * 80)          // 10240
#define STAGE_B   (A_BYTES + B_BYTES) // 20480
#define NSTAGES   5
#define SM_META   (NSTAGES * STAGE_B) // 102400
#define SMEM_TOTAL (SM_META + 1280)

// ---------------------------------------------------------------------------
// Device scratch (no runtime allocation)
// ---------------------------------------------------------------------------
__device__ __half d_Wh[O_ * KK_];     // weights fp16, [o][k'], k' = tap*256 + c
#define XPAD 16384
__device__ __half d_xt_buf[XPAD + (size_t)B_ * HW_ * C_ + XPAD]; // x^T: [b][hw][c]
__device__ int    d_mask_kind;        // 0=uint8, 1=int32, 2=float32

// ---------------------------------------------------------------------------
// Helpers
// ---------------------------------------------------------------------------
__device__ __forceinline__ uint32_t smem_to_u32(const void* p) {
    uint32_t a;
    asm("{ .reg .u64 t; cvta.to.shared.u64 t, %1; cvt.u32.u64 %0, t; }" : "=r"(a) : "l"(p));
    return a;
}

__device__ __forceinline__ void cp_async16(uint32_t dst, const void* src, int src_size) {
    asm volatile("cp.async.cg.shared.global [%0], [%1], 16, %2;"
                 :: "r"(dst), "l"(src), "r"(src_size) : "memory");
}
__device__ __forceinline__ void cp_commit() {
    asm volatile("cp.async.commit_group;" ::: "memory");
}
__device__ __forceinline__ void cp_wait3() {
    asm volatile("cp.async.wait_group 3;" ::: "memory");
}

// ---------------------------------------------------------------------------
// Mask dtype sniffing
// ---------------------------------------------------------------------------
__global__ void detect_mask_kernel(const unsigned int* __restrict__ pos) {
    __shared__ int any_big;
    __shared__ int any_f32;
    if (threadIdx.x == 0) { any_big = 0; any_f32 = 0; }
    __syncthreads();
    for (int i = threadIdx.x; i < 4096; i += 256) {
        unsigned int v = pos[i];
        if (v == 0x3F800000u) any_f32 = 1;
        else if (v > 1u)      any_big = 1;
    }
    __syncthreads();
    if (threadIdx.x == 0) d_mask_kind = any_f32 ? 2 : (any_big ? 0 : 1);
}

// ---------------------------------------------------------------------------
// Weights: masks (K,O) -> fp16 [o][k'] with k' = tap*256 + c   (k = c*9 + tap)
// ---------------------------------------------------------------------------
__global__ void prep_w_kernel(const void* __restrict__ posv,
                              const void* __restrict__ negv) {
    int i = blockIdx.x * 256 + threadIdx.x;   // over K*O
    if (i >= KK_ * O_) return;
    int k = i / O_;
    int o = i - k * O_;
    float p, n;
    int kind = d_mask_kind;
    if (kind == 1)      { p = (float)((const int*)posv)[i];   n = (float)((const int*)negv)[i]; }
    else if (kind == 2) { p = ((const float*)posv)[i];        n = ((const float*)negv)[i]; }
    else                { p = (float)((const unsigned char*)posv)[i];
                          n = (float)((const unsigned char*)negv)[i]; }
    int c = k / 9;
    int t = k - c * 9;
    d_Wh[o * KK_ + t * 256 + c] = __float2half(p - n);
}

// ---------------------------------------------------------------------------
// x (b,c,hw) fp32 -> x^T (b,hw,c) fp16, tiled SMEM transpose
// ---------------------------------------------------------------------------
__global__ void prep_xt_kernel(const float* __restrict__ x) {
    __shared__ __half tile[32][33];
    int hw0 = blockIdx.x * 32;
    int c0  = blockIdx.y * 32;
    int b   = blockIdx.z;
    int tx = threadIdx.x, ty = threadIdx.y;
    const float* xp = x + (size_t)b * C_ * HW_;
#pragma unroll
    for (int r = 0; r < 32; r += 8)
        tile[ty + r][tx] = __float2half(xp[(size_t)(c0 + ty + r) * HW_ + hw0 + tx]);
    __syncthreads();
    __half* xt = d_xt_buf + XPAD + (size_t)b * HW_ * C_;
#pragma unroll
    for (int r = 0; r < 32; r += 8)
        xt[(size_t)(hw0 + ty + r) * C_ + c0 + tx] = tile[tx][ty + r];
}

// ---------------------------------------------------------------------------
// Implicit-GEMM conv, wmma + 5-stage cp.async pipeline, 2 CTAs/SM.
// CTA: BM=128 o-channels x BN=128 pixels. 8 warps, warp grid 4(M) x 2(N),
// warp tile 32x64 -> acc[2][4] wmma 16x16x16 fragments (f16 in, f32 acc).
// K chunks: 72 x 32 (one tap x 32 contiguous channels in x^T layout).
// ---------------------------------------------------------------------------
__global__ __launch_bounds__(NTHREADS, 2)
void conv_gemm_kernel(float* __restrict__ out) {
    extern __shared__ __align__(1024) char smem[];
    const uint32_t smem_base = smem_to_u32(smem);
    const int tid = threadIdx.x;

    int* sXoff = (int*)(smem + SM_META);          // (b*HW + hw) * C
    int* sHW   = (int*)(smem + SM_META + 512);    // h<<16 | w
    int* sNB   = (int*)(smem + SM_META + 1024);   // per 4-pixel group: b*O*HW + hw

    const int n0 = blockIdx.x * BN;    // pixel tile
    const int m0 = blockIdx.y * BM;    // output-channel tile

    if (tid < BN) {
        int n  = n0 + tid;
        int b  = n / HW_;
        int hw = n - b * HW_;
        int h  = hw / W_;
        int w  = hw - h * W_;
        sXoff[tid] = (b * HW_ + hw) * C_;
        sHW[tid]   = (h << 16) | w;
    }
    if (tid < BN / 4) {
        int n  = n0 + 4 * tid;
        int b  = n / HW_;
        int hw = n - b * HW_;
        sNB[tid] = b * (O_ * HW_) + hw;
    }
    __syncthreads();

    // ---- stage loader: chunk i -> stage i % NSTAGES ----
    auto issue_loads = [&](int i) {
        const int s  = i % NSTAGES;
        const int t  = i >> 3;              // tap 0..8
        const int c0 = (i & 7) * BK;        // channel offset 0..224
        const int dh = t / 3 - 1;
        const int dw = t - (t / 3) * 3 - 1;
        // A: 512 tasks of 16B (128 rows x 4 segs); two per thread
        {
#pragma unroll
            for (int r = 0; r < 2; ++r) {
                int idx = tid + NTHREADS * r;
                int m   = idx >> 2;
                int seg = idx & 3;
                uint32_t dst = smem_base + s * STAGE_B + m * 80 + seg * 16;
                const __half* src = d_Wh + (size_t)(m0 + m) * KK_ + t * 256 + c0 + seg * 8;
                cp_async16(dst, src, 16);
            }
        }
        // B: 512 tasks of 16B (128 pixel-rows x 4 segs); two per thread
        {
            const int tapd = (dh * W_ + dw) * C_;
#pragma unroll
            for (int r = 0; r < 2; ++r) {
                int idx = tid + NTHREADS * r;
                int j   = idx >> 2;
                int seg = idx & 3;
                int hwp = sHW[j];
                int h = hwp >> 16, w = hwp & 0xFFFF;
                int valid = ((unsigned)(h + dh) < (unsigned)H_ &&
                             (unsigned)(w + dw) < (unsigned)W_) ? 16 : 0;
                uint32_t dst = smem_base + s * STAGE_B + A_BYTES + j * 80 + seg * 16;
                const __half* src = d_xt_buf + XPAD + sXoff[j] + tapd + c0 + seg * 8;
                cp_async16(dst, src, valid);
            }
        }
    };

    const int wid = tid >> 5;
    const int wm  = wid >> 1;   // 0..3 (M)
    const int wn  = wid & 1;    // 0..1 (N)

    wmma::fragment<wmma::accumulator, 16, 16, 16, float> acc[2][4];
#pragma unroll
    for (int im = 0; im < 2; ++im)
#pragma unroll
        for (int in = 0; in < 4; ++in)
            wmma::fill_fragment(acc[im][in], 0.0f);

    // ---- prologue: 4 stages in flight ----
#pragma unroll
    for (int i = 0; i < NSTAGES - 1; ++i) { issue_loads(i); cp_commit(); }

    // ---- main loop ----
    for (int i = 0; i < NCHUNK; ++i) {
        cp_wait3();
        __syncthreads();

        const int s = i % NSTAGES;
        const __half* as = (const __half*)(smem + s * STAGE_B);
        const __half* bs = (const __half*)(smem + s * STAGE_B + A_BYTES);
#pragma unroll
        for (int kk = 0; kk < BK; kk += 16) {
            wmma::fragment<wmma::matrix_a, 16, 16, 16, __half, wmma::row_major> af[2];
            wmma::fragment<wmma::matrix_b, 16, 16, 16, __half, wmma::col_major> bf[4];
#pragma unroll
            for (int im = 0; im < 2; ++im)
                wmma::load_matrix_sync(af[im], as + (wm * 32 + im * 16) * 40 + kk, 40);
#pragma unroll
            for (int in = 0; in < 4; ++in)
                wmma::load_matrix_sync(bf[in], bs + (wn * 64 + in * 16) * 40 + kk, 40);
#pragma unroll
            for (int im = 0; im < 2; ++im)
#pragma unroll
                for (int in = 0; in < 4; ++in)
                    wmma::mma_sync(acc[im][in], af[im], bf[in], acc[im][in]);
        }

        if (i + NSTAGES - 1 < NCHUNK) issue_loads(i + NSTAGES - 1);
        cp_commit();   // always commit (possibly empty) to keep wait_group math exact
    }
    __syncthreads();

    // ---- epilogue: 4 passes of 32 M-rows through SMEM, float4 scatter ----
    float* Cs = (float*)smem;   // [32][132]
#pragma unroll 1
    for (int pass = 0; pass < 4; ++pass) {
        if (wm == pass) {
#pragma unroll
            for (int im = 0; im < 2; ++im)
#pragma unroll
                for (int in = 0; in < 4; ++in)
                    wmma::store_matrix_sync(Cs + (im * 16) * 132 + wn * 64 + in * 16,
                                            acc[im][in], 132, wmma::mem_row_major);
        }
        __syncthreads();
#pragma unroll
        for (int r = 0; r < 4; ++r) {
            int e = tid + NTHREADS * r;       // 1024 float4 tasks
            int m = e >> 5;                   // 0..31 row
            int q = e & 31;                   // 4-pixel group
            float4 v = *(const float4*)(Cs + m * 132 + q * 4);
            *(float4*)(out + sNB[q] + (size_t)(m0 + pass * 32 + m) * HW_) = v;
        }
        __syncthreads();
    }
}

// ---------------------------------------------------------------------------
// Launch
// ---------------------------------------------------------------------------
extern "C" void kernel_launch(void* const* d_in, const int* in_sizes, int n_in,
                              void* d_out, int out_size) {
    const float* x   = (const float*)d_in[0];
    const void*  pos = d_in[1];
    const void*  neg = d_in[2];
    float* out = (float*)d_out;

    static bool attr_set = false;
    if (!attr_set) {
        cudaFuncSetAttribute(conv_gemm_kernel,
                             cudaFuncAttributeMaxDynamicSharedMemorySize, SMEM_TOTAL);
        attr_set = true;
    }

    // 0) sniff mask representation
    detect_mask_kernel<<<1, 256>>>((const unsigned int*)pos);
    // 1) weights -> fp16 [o][k'] (tap-major K permutation)
    prep_w_kernel<<<(KK_ * O_ + 255) / 256, 256>>>(pos, neg);
    // 2) x -> fp16 transposed [b][hw][c]
    dim3 tgrid(HW_ / 32, C_ / 32, B_);
    prep_xt_kernel<<<tgrid, dim3(32, 8)>>>(x);
    // 3) wmma implicit GEMM: grid = (784 pixel tiles, 4 m tiles), 2 CTAs/SM
    dim3 grid(NPIX / BN, O_ / BM);
    conv_gemm_kernel<<<grid, NTHREADS, SMEM_TOTAL>>>(out);
}